// round 9
// baseline (speedup 1.0000x reference)
#include <cuda_runtime.h>

#define Ll 4096
#define Dd 128
#define Cc 32
#define NCH 128
#define BHh 16
#define ELEMS (BHh*Ll*Dd)
#define O_ELEMS ((size_t)ELEMS)
#define NCHK (BHh*NCH)

typedef unsigned long long u64t;
__device__ __forceinline__ u64t pk2s(float a){
    u64t r; asm("mov.b64 %0,{%1,%1};" : "=l"(r) : "f"(a)); return r;
}
__device__ __forceinline__ u64t f2(u64t a, u64t b, u64t c){
    u64t d; asm("fma.rn.f32x2 %0,%1,%2,%3;" : "=l"(d) : "l"(a), "l"(b), "l"(c)); return d;
}
__device__ __forceinline__ float2 up2(u64t p){
    float lo, hi; asm("mov.b64 {%0,%1},%2;" : "=f"(lo), "=f"(hi) : "l"(p));
    return make_float2(lo, hi);
}

// Scratch
__device__ float g_qn [ELEMS];
__device__ float g_u  [ELEMS];
__device__ float g_w  [ELEMS];              // w row-major
__device__ float g_kT [NCHK*4096];          // k^T [d][32] per chunk
__device__ float g_att[NCHK*1024];
__device__ float g_S  [(size_t)NCHK*16384]; // S_i col-major [c][d]
__device__ float g_u2 [NCHK*4096];          // u' col-major [c][r]

// ----------------------------------------------------------------------------
// Kernel 1: per-chunk preprocessing. grid = 2048, block = 128
// ----------------------------------------------------------------------------
__global__ __launch_bounds__(128) void prep_kernel(
    const float* __restrict__ q, const float* __restrict__ k,
    const float* __restrict__ v, const float* __restrict__ beta)
{
    extern __shared__ float sm1[];
    float* sqT   = sm1;                // [128][33]
    float* skT   = sqT + 4224;         // [128][33]
    float* svb   = skT + 4224;         // [32][128]
    float* sA    = svb + 4096;         // [32][33]
    float* sbeta = sA  + 1056;         // [32]

    const int tid  = threadIdx.x;
    const int lane = tid & 31;
    const int warp = tid >> 5;
    const int bh = blockIdx.x >> 7;
    const int ci = blockIdx.x & 127;
    const int chk = blockIdx.x;
    const size_t base = ((size_t)bh*Ll + (size_t)ci*Cc)*Dd;

    for (int r = warp*8; r < warp*8 + 8; ++r) {
        float bet = beta[(size_t)bh*Ll + ci*Cc + r];
        const float4 xq = *(const float4*)(q + base + r*Dd + lane*4);
        const float4 xk = *(const float4*)(k + base + r*Dd + lane*4);
        const float4 xv = *(const float4*)(v + base + r*Dd + lane*4);
        float s2q = xq.x*xq.x + xq.y*xq.y + xq.z*xq.z + xq.w*xq.w;
        float s2k = xk.x*xk.x + xk.y*xk.y + xk.z*xk.z + xk.w*xk.w;
        #pragma unroll
        for (int o = 16; o; o >>= 1) {
            s2q += __shfl_xor_sync(0xffffffffu, s2q, o);
            s2k += __shfl_xor_sync(0xffffffffu, s2k, o);
        }
        float iq = rsqrtf(s2q + 1e-6f);
        float ik = rsqrtf(s2k + 1e-6f);
        float4 nq = make_float4(xq.x*iq, xq.y*iq, xq.z*iq, xq.w*iq);
        float4 nk = make_float4(xk.x*ik, xk.y*ik, xk.z*ik, xk.w*ik);
        *(float4*)(g_qn + base + r*Dd + lane*4) = nq;
        const int d0 = lane*4;
        sqT[(d0+0)*33 + r] = nq.x; sqT[(d0+1)*33 + r] = nq.y;
        sqT[(d0+2)*33 + r] = nq.z; sqT[(d0+3)*33 + r] = nq.w;
        skT[(d0+0)*33 + r] = nk.x; skT[(d0+1)*33 + r] = nk.y;
        skT[(d0+2)*33 + r] = nk.z; skT[(d0+3)*33 + r] = nk.w;
        *(float4*)(svb + r*Dd + d0) = make_float4(xv.x*bet, xv.y*bet, xv.z*bet, xv.w*bet);
        if (lane == 0) sbeta[r] = bet;
    }
    __syncthreads();

    {
        const int d = tid;
        #pragma unroll
        for (int r4 = 0; r4 < 32; r4 += 4) {
            *(float4*)&g_kT[(size_t)chk*4096 + d*32 + r4] = make_float4(
                skT[d*33+r4], skT[d*33+r4+1], skT[d*33+r4+2], skT[d*33+r4+3]);
        }
    }

    {
        const int i0 = (tid >> 3) * 2;
        const int j0 = (tid & 7) * 4;
        float a00=0,a01=0,a02=0,a03=0,a10=0,a11=0,a12=0,a13=0;
        float e00=0,e01=0,e02=0,e03=0,e10=0,e11=0,e12=0,e13=0;
        #pragma unroll 4
        for (int d = 0; d < Dd; ++d) {
            const float* kc = skT + d*33;
            const float* qc = sqT + d*33;
            float b0=kc[j0], b1=kc[j0+1], b2=kc[j0+2], b3=kc[j0+3];
            float ka0=kc[i0], ka1=kc[i0+1], qa0=qc[i0], qa1=qc[i0+1];
            a00+=ka0*b0; a01+=ka0*b1; a02+=ka0*b2; a03+=ka0*b3;
            a10+=ka1*b0; a11+=ka1*b1; a12+=ka1*b2; a13+=ka1*b3;
            e00+=qa0*b0; e01+=qa0*b1; e02+=qa0*b2; e03+=qa0*b3;
            e10+=qa1*b0; e11+=qa1*b1; e12+=qa1*b2; e13+=qa1*b3;
        }
        float nb0 = -sbeta[i0], nb1 = -sbeta[i0+1];
        sA[(i0  )*33+j0  ] = (j0  <i0  ) ? nb0*a00 : 0.f;
        sA[(i0  )*33+j0+1] = (j0+1<i0  ) ? nb0*a01 : 0.f;
        sA[(i0  )*33+j0+2] = (j0+2<i0  ) ? nb0*a02 : 0.f;
        sA[(i0  )*33+j0+3] = (j0+3<i0  ) ? nb0*a03 : 0.f;
        sA[(i0+1)*33+j0  ] = (j0  <i0+1) ? nb1*a10 : 0.f;
        sA[(i0+1)*33+j0+1] = (j0+1<i0+1) ? nb1*a11 : 0.f;
        sA[(i0+1)*33+j0+2] = (j0+2<i0+1) ? nb1*a12 : 0.f;
        sA[(i0+1)*33+j0+3] = (j0+3<i0+1) ? nb1*a13 : 0.f;
        float* ga = g_att + (size_t)chk*1024;
        ga[(i0  )*Cc+j0  ] = (j0  <=i0  ) ? e00 : 0.f;
        ga[(i0  )*Cc+j0+1] = (j0+1<=i0  ) ? e01 : 0.f;
        ga[(i0  )*Cc+j0+2] = (j0+2<=i0  ) ? e02 : 0.f;
        ga[(i0  )*Cc+j0+3] = (j0+3<=i0  ) ? e03 : 0.f;
        ga[(i0+1)*Cc+j0  ] = (j0  <=i0+1) ? e10 : 0.f;
        ga[(i0+1)*Cc+j0+1] = (j0+1<=i0+1) ? e11 : 0.f;
        ga[(i0+1)*Cc+j0+2] = (j0+2<=i0+1) ? e12 : 0.f;
        ga[(i0+1)*Cc+j0+3] = (j0+3<=i0+1) ? e13 : 0.f;
    }
    __syncthreads();

    if (warp == 0) {
        for (int i = 1; i < 32; ++i) {
            float rv  = sA[i*33 + lane];
            float acc = rv;
            for (int j = 0; j < i; ++j)
                acc += __shfl_sync(0xffffffffu, rv, j) * sA[j*33 + lane];
            sA[i*33 + lane] = acc;
            __syncwarp();
        }
        sA[lane*33 + lane] += 1.0f;
    }
    __syncthreads();

    {
        const int d = tid;
        #pragma unroll
        for (int rb = 0; rb < 4; ++rb) {
            const int r0 = rb*8;
            float ar[8];
            #pragma unroll
            for (int rr = 0; rr < 8; ++rr) ar[rr] = sA[(r0+rr)*33 + lane];
            float au[8] = {0,0,0,0,0,0,0,0};
            float aw[8] = {0,0,0,0,0,0,0,0};
            for (int j = 0; j < 32; ++j) {
                float vb = svb[j*Dd + d];
                float kb = skT[d*33 + j] * sbeta[j];
                #pragma unroll
                for (int rr = 0; rr < 8; ++rr) {
                    float a = __shfl_sync(0xffffffffu, ar[rr], j);
                    au[rr] += a*vb;
                    aw[rr] += a*kb;
                }
            }
            #pragma unroll
            for (int rr = 0; rr < 8; ++rr) {
                g_u[base + (size_t)(r0+rr)*Dd + d] = au[rr];
                g_w[base + (size_t)(r0+rr)*Dd + d] = aw[rr];
            }
        }
    }
}

// ----------------------------------------------------------------------------
// Kernel 2: sequential scan. grid = (16,16) = 256 CTAs, DVB=8, 2 CTAs/SM.
// ----------------------------------------------------------------------------
#define SWD 132
#define SKD 36
#define SST 12
#define SW_SZ (32*SWD)   // 4224
#define SK_SZ (128*SKD)  // 4608

__global__ __launch_bounds__(512, 2) void scan_kernel(float* __restrict__ out)
{
    extern __shared__ float sm2[];
    float* sw  = sm2;                   // [2][32][132]
    float* sk  = sw  + 2*SW_SZ;         // [2][128][36]
    float* sS  = sk  + 2*SK_SZ;         // [128][12]
    float* sYp = sS  + 1536;            // [8][32][12]
    float* su2 = sYp + 3072;            // [32][12]

    const int cb = blockIdx.x;          // 0..15
    const int bh = blockIdx.y;
    const int colbase = cb * 8;
    const int tid  = threadIdx.x;
    const int lane = tid & 31;
    const int warp = tid >> 5;

    // Y roles: dq 0..7 (16-d slice), ch4 = 0/4 (col half); lane = r
    const int dq  = warp >> 1;
    const int ch4 = (warp & 1) * 4;
    // update roles: ud 0..3 (32-d), uc2 = col pair 0,2,4,6
    const int ud  = warp >> 2;
    const int uc2 = (warp & 3) * 2;
    const int sd  = ud*32 + lane;
    // u' roles (tid<64): r=tid&31, uh4=(tid>>5)*4
    const int uh4 = (tid >> 5) * 4;
    // staging roles
    const int wm  = tid >> 4;           // 0..31
    const int wd0 = (tid & 15) * 8;
    const int kd  = tid >> 2;           // 0..127
    const int kr0 = (tid & 3) * 8;

    u64t s01 = 0ull;                    // S[sd][colbase+uc2 .. +1]
    for (int i = tid; i < 1536; i += 512) sS[i] = 0.f;

    float4 rw0, rw1, rk0, rk1, ru;

    // prefetch + commit chunk 0
    {
        const size_t pb = ((size_t)bh*Ll)*Dd;
        rw0 = *(const float4*)(g_w + pb + wm*Dd + wd0);
        rw1 = *(const float4*)(g_w + pb + wm*Dd + wd0 + 4);
        rk0 = *(const float4*)(g_kT + (size_t)(bh*NCH)*4096 + kd*32 + kr0);
        rk1 = *(const float4*)(g_kT + (size_t)(bh*NCH)*4096 + kd*32 + kr0 + 4);
        if (tid < 64)
            ru = *(const float4*)(g_u + pb + (size_t)(tid&31)*Dd + colbase + uh4);
        *(float4*)&sw[wm*SWD + wd0    ] = rw0;
        *(float4*)&sw[wm*SWD + wd0 + 4] = rw1;
        *(float4*)&sk[kd*SKD + kr0    ] = rk0;
        *(float4*)&sk[kd*SKD + kr0 + 4] = rk1;
    }
    __syncthreads();

    for (int ci = 0; ci < NCH; ++ci) {
        const int buf = ci & 1;
        const int chk = bh*NCH + ci;

        // persist S_i (pre-chunk), col-major [c][d]
        {
            float2 a = up2(s01);
            float* gs = g_S + (size_t)chk*16384 + (size_t)(colbase + uc2)*128 + sd;
            gs[0] = a.x; gs[128] = a.y;
        }
        // prefetch chunk ci+1
        float4 ru_next = ru;
        if (ci + 1 < NCH) {
            const size_t pb = ((size_t)bh*Ll + (size_t)(ci+1)*Cc)*Dd;
            rw0 = *(const float4*)(g_w + pb + wm*Dd + wd0);
            rw1 = *(const float4*)(g_w + pb + wm*Dd + wd0 + 4);
            rk0 = *(const float4*)(g_kT + (size_t)(chk+1)*4096 + kd*32 + kr0);
            rk1 = *(const float4*)(g_kT + (size_t)(chk+1)*4096 + kd*32 + kr0 + 4);
            if (tid < 64)
                ru_next = *(const float4*)(g_u + pb + (size_t)(tid&31)*Dd + colbase + uh4);
        }

        // Y: partial of w(32x128)@S(128x8); warp: d in [dq*16,+16), 4 cols
        {
            const float* bw = sw + buf*SW_SZ + lane*SWD + dq*16;
            u64t y0 = 0ull, y1 = 0ull;
            #pragma unroll
            for (int j4 = 0; j4 < 4; ++j4) {
                float4 wv = *(const float4*)(bw + j4*4);
                #pragma unroll
                for (int i = 0; i < 4; ++i) {
                    float xs = (i==0)?wv.x:(i==1)?wv.y:(i==2)?wv.z:wv.w;
                    u64t xx = pk2s(xs);
                    ulonglong2 sv = *(const ulonglong2*)&sS[(dq*16 + j4*4 + i)*SST + ch4];
                    y0 = f2(xx, sv.x, y0);
                    y1 = f2(xx, sv.y, y1);
                }
            }
            ulonglong2 o; o.x = y0; o.y = y1;
            *(ulonglong2*)&sYp[dq*384 + lane*SST + ch4] = o;
        }
        __syncthreads();

        // u' = u - w@S  (tid<64)
        if (tid < 64) {
            const int r = tid & 31;
            float4 acc = ru;
            #pragma unroll
            for (int d8 = 0; d8 < 8; ++d8) {
                float4 p = *(const float4*)&sYp[d8*384 + r*SST + uh4];
                acc.x -= p.x; acc.y -= p.y; acc.z -= p.z; acc.w -= p.w;
            }
            *(float4*)&su2[r*SST + uh4] = acc;
            float* gu = g_u2 + (size_t)chk*4096 + (colbase + uh4)*32 + r;
            gu[0] = acc.x; gu[32] = acc.y; gu[64] = acc.z; gu[96] = acc.w;
        }
        // commit next chunk into other buffer (overlaps u')
        if (ci + 1 < NCH) {
            const int b2 = (ci+1) & 1;
            float* dw = sw + b2*SW_SZ;
            float* dk = sk + b2*SK_SZ;
            *(float4*)&dw[wm*SWD + wd0    ] = rw0;
            *(float4*)&dw[wm*SWD + wd0 + 4] = rw1;
            *(float4*)&dk[kd*SKD + kr0    ] = rk0;
            *(float4*)&dk[kd*SKD + kr0 + 4] = rk1;
            ru = ru_next;
        }
        __syncthreads();

        // S += k^T @ u'  (16 warps, tile 32d x 2c, packed accumulator)
        {
            const float* kp = sk + buf*SK_SZ + sd*SKD;
            #pragma unroll
            for (int r4 = 0; r4 < 8; ++r4) {
                float4 k4 = *(const float4*)(kp + r4*4);
                #pragma unroll
                for (int i = 0; i < 4; ++i) {
                    float ks = (i==0)?k4.x:(i==1)?k4.y:(i==2)?k4.z:k4.w;
                    u64t kk = pk2s(ks);
                    u64t uu = *(const u64t*)&su2[(r4*4 + i)*SST + uc2];
                    s01 = f2(kk, uu, s01);
                }
            }
            *(u64t*)&sS[sd*SST + uc2] = s01;
        }
        __syncthreads();
    }

    // final S -> out
    {
        float2 a = up2(s01);
        *(float2*)&out[O_ELEMS + ((size_t)bh*Dd + sd)*Dd + colbase + uc2] = a;
    }
}

// ----------------------------------------------------------------------------
// Kernel 3: epilogue o = q@S_i + A@u'_i. grid = (NCH, BHh), block = 256.
// ----------------------------------------------------------------------------
#define AST 36

__global__ __launch_bounds__(256) void epi_kernel(float* __restrict__ out)
{
    extern __shared__ float sm3[];
    float* sS = sm3;              // [128][132]
    float* sq = sS + 128*132;     // [32][132]
    float* su = sq + 32*132;      // [32][132]
    float* sA = su + 32*132;      // [32][36]

    const int ci = blockIdx.x;
    const int bh = blockIdx.y;
    const int chk = bh*NCH + ci;
    const int tid = threadIdx.x;
    const size_t qbase = ((size_t)bh*Ll + (size_t)ci*Cc)*Dd;

    {
        const int c = tid >> 1;
        const int db = (tid & 1) * 64;
        const float* gs = g_S + (size_t)chk*16384 + (size_t)c*128 + db;
        #pragma unroll
        for (int i = 0; i < 16; ++i) {
            float4 f = *(const float4*)(gs + i*4);
            int d = db + i*4;
            sS[(d  )*132 + c] = f.x; sS[(d+1)*132 + c] = f.y;
            sS[(d+2)*132 + c] = f.z; sS[(d+3)*132 + c] = f.w;
        }
    }
    {
        #pragma unroll
        for (int t = 0; t < 4; ++t) {
            int i4 = (tid + t*256) * 4;
            float4 f = *(const float4*)(g_qn + qbase + i4);
            *(float4*)&sq[(i4 >> 7)*132 + (i4 & 127)] = f;
        }
    }
    {
        #pragma unroll
        for (int t = 0; t < 4; ++t) {
            int i4 = (tid + t*256) * 4;
            float4 f = *(const float4*)(g_u2 + (size_t)chk*4096 + i4);
            int c = i4 >> 5, r = i4 & 31;
            su[(r  )*132 + c] = f.x; su[(r+1)*132 + c] = f.y;
            su[(r+2)*132 + c] = f.z; su[(r+3)*132 + c] = f.w;
        }
    }
    {
        int i4 = tid * 4;
        float4 f = *(const float4*)(g_att + (size_t)chk*1024 + i4);
        *(float4*)&sA[(i4 >> 5)*AST + (i4 & 31)] = f;
    }
    __syncthreads();

    const int m0 = (tid >> 4) * 2;
    const int m1 = m0 + 1;
    const int cbk = (tid & 15) * 8;
    float4 a00 = make_float4(0,0,0,0), a01 = a00, a10 = a00, a11 = a00;
    #pragma unroll 8
    for (int d = 0; d < 128; ++d) {
        float q0 = sq[m0*132 + d];
        float q1 = sq[m1*132 + d];
        float4 s0 = *(const float4*)&sS[d*132 + cbk];
        float4 s1 = *(const float4*)&sS[d*132 + cbk + 4];
        a00.x += q0*s0.x; a00.y += q0*s0.y; a00.z += q0*s0.z; a00.w += q0*s0.w;
        a01.x += q0*s1.x; a01.y += q0*s1.y; a01.z += q0*s1.z; a01.w += q0*s1.w;
        a10.x += q1*s0.x; a10.y += q1*s0.y; a10.z += q1*s0.z; a10.w += q1*s0.w;
        a11.x += q1*s1.x; a11.y += q1*s1.y; a11.z += q1*s1.z; a11.w += q1*s1.w;
    }
    #pragma unroll 8
    for (int j = 0; j < 32; ++j) {
        float p0 = sA[m0*AST + j];
        float p1 = sA[m1*AST + j];
        float4 u0 = *(const float4*)&su[j*132 + cbk];
        float4 u1 = *(const float4*)&su[j*132 + cbk + 4];
        a00.x += p0*u0.x; a00.y += p0*u0.y; a00.z += p0*u0.z; a00.w += p0*u0.w;
        a01.x += p0*u1.x; a01.y += p0*u1.y; a01.z += p0*u1.z; a01.w += p0*u1.w;
        a10.x += p1*u0.x; a10.y += p1*u0.y; a10.z += p1*u0.z; a10.w += p1*u0.w;
        a11.x += p1*u1.x; a11.y += p1*u1.y; a11.z += p1*u1.z; a11.w += p1*u1.w;
    }
    float* o0 = out + qbase + (size_t)m0*Dd + cbk;
    float* o1 = out + qbase + (size_t)m1*Dd + cbk;
    *(float4*)(o0)     = a00; *(float4*)(o0 + 4) = a01;
    *(float4*)(o1)     = a10; *(float4*)(o1 + 4) = a11;
}

// ----------------------------------------------------------------------------
extern "C" void kernel_launch(void* const* d_in, const int* in_sizes, int n_in,
                              void* d_out, int out_size)
{
    const float* q    = (const float*)d_in[0];
    const float* k    = (const float*)d_in[1];
    const float* v    = (const float*)d_in[2];
    const float* beta = (const float*)d_in[3];
    float* out = (float*)d_out;

    const int smem1 = (2*4224 + 4096 + 1056 + 32) * 4;                 // 54528
    const int smem2 = (2*SW_SZ + 2*SK_SZ + 1536 + 3072 + 384) * 4;     // 90624
    const int smem3 = (128*132 + 32*132 + 32*132 + 32*AST) * 4;        // 105984
    cudaFuncSetAttribute(prep_kernel, cudaFuncAttributeMaxDynamicSharedMemorySize, smem1);
    cudaFuncSetAttribute(scan_kernel, cudaFuncAttributeMaxDynamicSharedMemorySize, smem2);
    cudaFuncSetAttribute(epi_kernel,  cudaFuncAttributeMaxDynamicSharedMemorySize, smem3);

    prep_kernel<<<NCHK, 128, smem1>>>(q, k, v, beta);
    scan_kernel<<<dim3(16, BHh), 512, smem2>>>(out);
    epi_kernel<<<dim3(NCH, BHh), 256, smem3>>>(out);
}